// round 4
// baseline (speedup 1.0000x reference)
#include <cuda_runtime.h>
#include <cstdint>

// ---------------------------------------------------------------------------
// Block-diagonal linear (irreps 256x0e+256x1o+256x2e) as 3 GEMMs over rows
// (z,i):  M_b = B*d_b, N=256, K=256.
//   A'[z*d+i][u] = feat[z, xoff_b + u*d + i]
//   C = A' * W_b * (1/16), scattered back with the same (z,i) row mapping.
// mma.sync m16n8k8 tf32. This round: cvt hoisted to staging, fragment-order
// smem layouts (LDS.128), software-prefetch staging (LDG->cvt->STS),
// one barrier per k-chunk.
// ---------------------------------------------------------------------------
#define HX_B    50000
#define HX_FEAT 2304

static constexpr int TM = 128;         // rows per CTA
static constexpr int KC = 32;          // k-chunk
static constexpr int NCHUNK = 256 / KC;
static constexpr int NTHREADS = 512;   // 16 warps: wm=wid&3 (M), wn=wid>>2 (N)

// tiles: ceil(50000/128)=391, ceil(150000/128)=1172, ceil(250000/128)=1954
static constexpr int T0 = 391, T1 = 391 + 1172, T2 = 391 + 1172 + 1954; // 3517

// smem (bytes): fragment-order buffers
//   A chunk: 1024 vec4 (16 KB)  index v=(s*8+rb)*32+lane
//   B chunk: 2048 vec4 (32 KB)  index v=((s*4+wn)*4+nfp)*32+lane
static constexpr int A_CH = 16384;
static constexpr int B_CH = 32768;
static constexpr int OFF_A0 = 0;
static constexpr int OFF_A1 = A_CH;
static constexpr int OFF_B0 = 2 * A_CH;
static constexpr int OFF_B1 = 2 * A_CH + B_CH;
static constexpr int SM_BYTES = 2 * A_CH + 2 * B_CH;   // 98304

// ---------------------------------------------------------------------------
__device__ __forceinline__ uint32_t f2tf(float x) {
    uint32_t r;
    asm("cvt.rna.tf32.f32 %0, %1;" : "=r"(r) : "f"(x));
    return r;
}

__device__ __forceinline__ void mma8(float* c, const uint32_t* a,
                                     uint32_t b0, uint32_t b1) {
    asm volatile(
        "mma.sync.aligned.m16n8k8.row.col.f32.tf32.tf32.f32 "
        "{%0,%1,%2,%3}, {%4,%5,%6,%7}, {%8,%9}, {%0,%1,%2,%3};"
        : "+f"(c[0]), "+f"(c[1]), "+f"(c[2]), "+f"(c[3])
        : "r"(a[0]), "r"(a[1]), "r"(a[2]), "r"(a[3]), "r"(b0), "r"(b1));
}

// ---------------------------------------------------------------------------
__global__ void __launch_bounds__(NTHREADS, 1)
linear_mma_kernel(const float* __restrict__ feat,
                  const float* __restrict__ wt,
                  float* __restrict__ out)
{
    extern __shared__ char smem[];

    const int tid  = threadIdx.x;
    const int wid  = tid >> 5;
    const int lane = tid & 31;
    const int g    = lane >> 2;
    const int tg   = lane & 3;
    const int wm   = wid & 3;
    const int wn   = wid >> 2;

    // ---- block / tile decode ----
    const int bid = blockIdx.x;
    int d, xoff, woff, Mtot, m0;
    if (bid < T0)      { d = 1; xoff = 0;    woff = 0;      Mtot = 50000;  m0 = bid * TM; }
    else if (bid < T1) { d = 3; xoff = 256;  woff = 65536;  Mtot = 150000; m0 = (bid - T0) * TM; }
    else               { d = 5; xoff = 1024; woff = 131072; Mtot = 250000; m0 = (bid - T1) * TM; }

    const float* wblk = wt + woff;

    // ---- precompute A staging geometry: 2 vec4 per thread ----
    // v = tid + 512*p: v = (s*8+rb)*32 + l;  vec4 elements:
    //   (row=rb*16+g,   k=s*8+tg), (row+8, k), (row, k+4), (row+8, k+4)
    int a_base0[2], a_base1[2], a_k0[2];
    bool a_v0[2], a_v1[2];
    #pragma unroll
    for (int p = 0; p < 2; p++) {
        const int v = tid + NTHREADS * p;
        const int l = v & 31, gg = l >> 2, tt = l & 3;
        const int s_rb = v >> 5;
        const int s = s_rb >> 3, rb = s_rb & 7;
        const int r0 = rb * 16 + gg;
        const int rg0 = m0 + r0, rg1 = rg0 + 8;
        a_k0[p] = s * 8 + tt;
        a_v0[p] = rg0 < Mtot;
        a_v1[p] = rg1 < Mtot;
        a_base0[p] = a_v0[p] ? ((rg0 / d) * HX_FEAT + xoff + rg0 % d) : 0;
        a_base1[p] = a_v1[p] ? ((rg1 / d) * HX_FEAT + xoff + rg1 % d) : 0;
    }

    // ---- precompute B staging geometry: 4 vec4 per thread ----
    // v = tid + 512*p: v = ((s*4+wn)*4+nfp)*32 + l; vec4:
    //   (k=s*8+tg, n), (k+4, n), (k, n+8), (k+4, n+8),  n = wn*64+nfp*16+g
    int b_base[4];
    #pragma unroll
    for (int p = 0; p < 4; p++) {
        const int v = tid + NTHREADS * p;
        const int l = v & 31, gg = l >> 2, tt = l & 3;
        const int nfp = (v >> 5) & 3;
        const int sw = v >> 7;
        const int s = sw >> 2, wnn = sw & 3;
        const int k0 = s * 8 + tt;
        const int n0 = wnn * 64 + nfp * 16 + gg;
        b_base[p] = k0 * 256 + n0;
    }

    // ---- staging registers ----
    float sa[2][4];
    float sb[4][4];

    auto stage_regs = [&](int u0) {
        #pragma unroll
        for (int p = 0; p < 2; p++) {
            const int ka = (u0 + a_k0[p]) * d;
            const int kb = ka + 4 * d;
            sa[p][0] = a_v0[p] ? __ldg(feat + a_base0[p] + ka) : 0.0f;
            sa[p][1] = a_v1[p] ? __ldg(feat + a_base1[p] + ka) : 0.0f;
            sa[p][2] = a_v0[p] ? __ldg(feat + a_base0[p] + kb) : 0.0f;
            sa[p][3] = a_v1[p] ? __ldg(feat + a_base1[p] + kb) : 0.0f;
        }
        const int uo = u0 * 256;
        #pragma unroll
        for (int p = 0; p < 4; p++) {
            const float* bp = wblk + uo + b_base[p];
            sb[p][0] = __ldg(bp);
            sb[p][1] = __ldg(bp + 1024);   // k+4
            sb[p][2] = __ldg(bp + 8);      // n+8
            sb[p][3] = __ldg(bp + 1032);
        }
    };

    auto commit = [&](uint32_t aoff, uint32_t boff) {
        uint4* Ad = (uint4*)(smem + aoff);
        uint4* Bd = (uint4*)(smem + boff);
        #pragma unroll
        for (int p = 0; p < 2; p++) {
            uint4 q;
            q.x = f2tf(sa[p][0]); q.y = f2tf(sa[p][1]);
            q.z = f2tf(sa[p][2]); q.w = f2tf(sa[p][3]);
            Ad[tid + NTHREADS * p] = q;
        }
        #pragma unroll
        for (int p = 0; p < 4; p++) {
            uint4 q;
            q.x = f2tf(sb[p][0]); q.y = f2tf(sb[p][1]);
            q.z = f2tf(sb[p][2]); q.w = f2tf(sb[p][3]);
            Bd[tid + NTHREADS * p] = q;
        }
    };

    // ---- accumulators ----
    float c[2][8][4];
    #pragma unroll
    for (int mf = 0; mf < 2; mf++)
        #pragma unroll
        for (int nf = 0; nf < 8; nf++)
            #pragma unroll
            for (int q = 0; q < 4; q++) c[mf][nf][q] = 0.0f;

    auto compute = [&](uint32_t aoff, uint32_t boff) {
        const uint4* Ab = (const uint4*)(smem + aoff);
        const uint4* Bb = (const uint4*)(smem + boff);
        #pragma unroll
        for (int s = 0; s < 4; s++) {
            uint4 a0 = Ab[(s * 8 + wm * 2 + 0) * 32 + lane];
            uint4 a1 = Ab[(s * 8 + wm * 2 + 1) * 32 + lane];
            #pragma unroll
            for (int nfp = 0; nfp < 4; nfp++) {
                const uint4 bf = Bb[((s * 4 + wn) * 4 + nfp) * 32 + lane];
                mma8(c[0][2 * nfp],     (const uint32_t*)&a0, bf.x, bf.y);
                mma8(c[1][2 * nfp],     (const uint32_t*)&a1, bf.x, bf.y);
                mma8(c[0][2 * nfp + 1], (const uint32_t*)&a0, bf.z, bf.w);
                mma8(c[1][2 * nfp + 1], (const uint32_t*)&a1, bf.z, bf.w);
            }
        }
    };

    // ---- pipeline: stage 0 -> smem; LDG chunk 1; loop ----
    stage_regs(0);
    commit(OFF_A0, OFF_B0);
    __syncthreads();
    stage_regs(KC);

    #pragma unroll 1
    for (int ch = 0; ch < NCHUNK; ch++) {
        const uint32_t aoff = (ch & 1) ? OFF_A1 : OFF_A0;
        const uint32_t boff = (ch & 1) ? OFF_B1 : OFF_B0;
        compute(aoff, boff);                 // overlaps in-flight LDGs of ch+1
        if (ch + 1 < NCHUNK) {
            commit((ch & 1) ? OFF_A0 : OFF_A1,
                   (ch & 1) ? OFF_B0 : OFF_B1);
            __syncthreads();
            if (ch + 2 < NCHUNK) stage_regs((ch + 2) * KC);
        }
    }

    // ---- epilogue: scatter rows (z,i), scale 1/sqrt(256) ----
    const float SCALE = 0.0625f;
    #pragma unroll
    for (int mf = 0; mf < 2; mf++) {
        const int row_lo = wm * 32 + mf * 16 + g;
        #pragma unroll
        for (int rr = 0; rr < 2; rr++) {
            const int rg = m0 + row_lo + rr * 8;
            if (rg < Mtot) {
                const int z = rg / d, i = rg % d;
                float* op = out + (size_t)z * HX_FEAT + xoff + i;
                #pragma unroll
                for (int nf = 0; nf < 8; nf++) {
                    const int n0 = wn * 64 + nf * 8 + 2 * tg;
                    op[(size_t)n0 * d]       = c[mf][nf][rr * 2 + 0] * SCALE;
                    op[(size_t)(n0 + 1) * d] = c[mf][nf][rr * 2 + 1] * SCALE;
                }
            }
        }
    }
}

// ---------------------------------------------------------------------------
extern "C" void kernel_launch(void* const* d_in, const int* in_sizes, int n_in,
                              void* d_out, int out_size) {
    const float* feat = (const float*)d_in[0];
    const float* wt   = (const float*)d_in[1];
    float* out        = (float*)d_out;

    cudaFuncSetAttribute(linear_mma_kernel,
                         cudaFuncAttributeMaxDynamicSharedMemorySize, SM_BYTES);

    linear_mma_kernel<<<T2, NTHREADS, SM_BYTES>>>(feat, wt, out);
}